// round 16
// baseline (speedup 1.0000x reference)
#include <cuda_runtime.h>
#include <math.h>

#define BB 64
#define NN 512
#define DD 128
#define UU 64
#define NB 64
#define NSTEPS (NN/NB)

#define PSTRIDE 449              // odd -> conflict-free transposed panel stores
#define OFF_S   28736            // 64*449 (P panel)
#define OFF_X   (OFF_S + 64*65)
#define OFF_XT  (OFF_X + 64*65)
#define OFF_TT  (OFF_XT + 64*65)
#define OFF_DI  (OFF_TT + 32*33)
#define SMEM_FLOATS (OFF_DI + 64)
#define SMEM_BYTES (SMEM_FLOATS*4)

#define PTROW 448                // g_PT row stride (max panel height)

// Scratch (allocation-free rule: __device__ globals)
__device__ float g_M[BB*NN*NN];              // Cholesky workspace (copy of A)
__device__ float g_chi[BB*NN];
__device__ float g_Linv[NSTEPS*BB*NB*NB];    // inv of each diagonal block L11
__device__ float g_LinvT[NSTEPS*BB*NB*NB];   // transposed inverses (backward diag)
__device__ float g_PT[(size_t)NSTEPS*BB*NB*PTROW];  // L21^T panels (backward solve)
__device__ float g_xv[BB*NN];                // x2 handoff (rank1 -> rank0)

__device__ __forceinline__ float tshrink(float x) { return x - tanhf(x); }

#define CLUSTER_SYNC() do { \
    asm volatile("barrier.cluster.arrive.aligned;" ::: "memory"); \
    asm volatile("barrier.cluster.wait.aligned;" ::: "memory"); \
} while(0)

// ---------------------------------------------------------------------------
// Build A (B,N,N): 32x32 tile per block, write to output AND scratch
// ---------------------------------------------------------------------------
__global__ __launch_bounds__(256) void buildA_kernel(
    const float* __restrict__ pos,
    const int*   __restrict__ ntype,
    const float* __restrict__ hardness,
    const float* __restrict__ sigma,
    float* __restrict__ outA)
{
    __shared__ float pix[32], piy[32], piz[32];
    __shared__ float pjx[32], pjy[32], pjz[32];
    __shared__ float si[32], sj[32], hi[32];

    const int b  = blockIdx.z;
    const int it = blockIdx.y, jt = blockIdx.x;
    const int tid = threadIdx.x;
    const float kC = 14.399645351950548f;

    if (tid < 32) {
        int gi = it*32 + tid;
        const float* p = pos + ((size_t)b*NN + gi)*3;
        pix[tid]=p[0]; piy[tid]=p[1]; piz[tid]=p[2];
        int t = ntype[b*NN + gi];
        si[tid] = sigma[t]; hi[tid] = hardness[t];
    } else if (tid < 64) {
        int l = tid - 32;
        int gj = jt*32 + l;
        const float* p = pos + ((size_t)b*NN + gj)*3;
        pjx[l]=p[0]; pjy[l]=p[1]; pjz[l]=p[2];
        sj[l] = sigma[ntype[b*NN + gj]];
    }
    __syncthreads();

    float* Ab = outA + (size_t)b*NN*NN;
    float* Mb = g_M  + (size_t)b*NN*NN;

    for (int e = tid; e < 32*32; e += 256) {
        int li = e >> 5, lj = e & 31;
        int i = it*32 + li, j = jt*32 + lj;
        float dx = pix[li]-pjx[lj], dy = piy[li]-pjy[lj], dz = piz[li]-pjz[lj];
        float dist = sqrtf(dx*dx + dy*dy + dz*dz) + 1e-8f;
        float g2 = si[li]*si[li] + sj[lj]*sj[lj];
        float arg = dist * rsqrtf(2.0f * g2);
        float a = kC * erff(arg) / dist;
        if (i == j) {
            a += hi[li] + kC / (1.7724538509055159f * 1.4142135623730951f * si[li]);
        }
        size_t off = (size_t)i*NN + j;
        Ab[off] = a;
        Mb[off] = a;
    }
}

// ---------------------------------------------------------------------------
// Fused per-batch Cholesky + triangular solves + Schur combine.
// 2-CTA cluster per batch. Rank 0: potrf; rank 1: chi chunk (hidden).
// NEW vs R15: coalesced dump of the post-trsm panel (= L21^T) into g_PT,
// and a stagingless, barrier-free backward-solve t-loop reading g_PT.
// ---------------------------------------------------------------------------
extern __shared__ float sh[];

__global__ __launch_bounds__(512, 1) __cluster_dims__(2, 1, 1)
void factor_solve_kernel(const float* __restrict__ tq, float* __restrict__ outC,
                         const float* __restrict__ nf,
                         const float* __restrict__ W1, const float* __restrict__ b1,
                         const float* __restrict__ W2, const float* __restrict__ b2,
                         const float* __restrict__ W3, const float* __restrict__ b3)
{
    const int b    = blockIdx.x >> 1;
    const int rank = blockIdx.x & 1;
    const int tid  = threadIdx.x;  // 512
    float* Mb = g_M + (size_t)b*NN*NN;

    float* P  = sh;
    float* Sd = sh + OFF_S;    // [64][65] diag block
    float* Xi = sh + OFF_X;    // [64][65] invL
    float* Xt = sh + OFF_XT;   // [64][65] invL transposed
    float* Tt = sh + OFF_TT;   // [32][33]
    float* di = sh + OFF_DI;   // [64]

    // ======================= FACTORIZATION =======================
    for (int s = 0; s < NSTEPS; s++) {
        const int k0 = s*NB;
        const int R  = NSTEPS - 1 - s;

        if (rank == 0) {
            // ---- load diagonal block
            for (int idx = tid; idx < NB*NB; idx += 512)
                Sd[(idx>>6)*65 + (idx&63)] = Mb[(size_t)(k0 + (idx>>6))*NN + k0 + (idx&63)];
            __syncthreads();

            // ---- LDL-style elimination, 1 barrier/iter, all 512 threads
            for (int j = 0; j < NB; j++) {
                float invd = 1.0f / Sd[j*65 + j];
                int cnt = (63 - j) * 64;
                for (int idx = tid; idx < cnt; idx += 512) {
                    int i = j + 1 + (idx>>6), c = idx & 63;
                    if (c > j && i >= c)
                        Sd[i*65 + c] -= Sd[i*65 + j] * (Sd[c*65 + j] * invd);
                }
                __syncthreads();
            }
            if (tid < NB) di[tid] = rsqrtf(Sd[tid*65 + tid]);
            __syncthreads();
            for (int idx = tid; idx < NB*NB; idx += 512) {
                int i = idx>>6, c = idx & 63;
                if (i >= c) Sd[i*65 + c] *= di[c];
            }
            __syncthreads();

            // ---- invert L11 (block 2x2): two warp-local 32x32 inversions
            if (tid < 64) {
                int h = tid >> 5, j = tid & 31, base = h*32;
                for (int i = 0; i < 32; i++) {
                    float acc = (i == j) ? 1.0f : 0.0f;
                    for (int p = 0; p < i; p++)
                        acc -= Sd[(base+i)*65 + base+p] * Xi[(base+p)*65 + base+j];
                    Xi[(base+i)*65 + base+j] = acc * di[base+i];
                    __syncwarp();
                }
            }
            __syncthreads();
            for (int idx = tid; idx < 32*32; idx += 512) {
                int i = idx>>5, j = idx & 31;
                float acc = 0.0f;
                #pragma unroll 8
                for (int p = 0; p < 32; p++) acc += Sd[(32+i)*65 + p] * Xi[p*65 + j];
                Tt[i*33 + j] = acc;
                Xi[i*65 + 32 + j] = 0.0f;
            }
            __syncthreads();
            for (int idx = tid; idx < 32*32; idx += 512) {
                int i = idx>>5, j = idx & 31;
                float acc = 0.0f;
                #pragma unroll 8
                for (int p = 0; p < 32; p++) acc += Xi[(32+i)*65 + 32+p] * Tt[p*33 + j];
                Xi[(32+i)*65 + j] = -acc;
            }
            __syncthreads();

            // write g_Linv/g_LinvT (coalesced) + smem Xt[k][j] = invL[j][k]
            {
                float* Xb  = g_Linv  + ((size_t)s*BB + b)*NB*NB;
                float* XbT = g_LinvT + ((size_t)s*BB + b)*NB*NB;
                for (int idx = tid; idx < NB*NB; idx += 512) {
                    int i = idx>>6, j = idx & 63;
                    float v = Xi[i*65 + j];
                    Xb[idx] = v;
                    Xt[j*65 + i] = v;
                    XbT[idx] = Xi[j*65 + i];
                }
            }
            __syncthreads();
        } else {
            // ---- rank 1: chi MLP for rows s*64 .. s*64+63 of batch b.
            const int h  = tid >> 8;          // 0 or 1
            const int t2 = tid & 255;
            float* xs = P + h*9216;           // [128][36]
            float* h1 = xs + 4608;            // [64][36]
            float* h2 = xs + 6912;            // [64][36]
            const int grow0 = b*NN + s*64 + h*32;
            const int u0 = 2*(t2 >> 3);
            const int r0 = 4*(t2 & 7);

            #pragma unroll
            for (int t = 0; t < 4; t++) {
                int f = t2 + 256*t;
                int r = f >> 5, c4 = f & 31;
                float4 v = *(const float4*)(nf + (size_t)(grow0 + r)*DD + c4*4);
                xs[(c4*4+0)*36 + r] = v.x;
                xs[(c4*4+1)*36 + r] = v.y;
                xs[(c4*4+2)*36 + r] = v.z;
                xs[(c4*4+3)*36 + r] = v.w;
            }
            __syncthreads();

            // layer 1
            {
                float2 bb = *(const float2*)&b1[u0];
                float acc0[4] = {bb.x, bb.x, bb.x, bb.x};
                float acc1[4] = {bb.y, bb.y, bb.y, bb.y};
                #pragma unroll 4
                for (int d = 0; d < DD; d++) {
                    float2 w = *(const float2*)&W1[d*UU + u0];
                    float4 xa = *(const float4*)&xs[d*36 + r0];
                    acc0[0] += xa.x*w.x; acc0[1] += xa.y*w.x; acc0[2] += xa.z*w.x; acc0[3] += xa.w*w.x;
                    acc1[0] += xa.x*w.y; acc1[1] += xa.y*w.y; acc1[2] += xa.z*w.y; acc1[3] += xa.w*w.y;
                }
                *(float4*)&h1[u0*36 + r0] =
                    make_float4(tshrink(acc0[0]), tshrink(acc0[1]), tshrink(acc0[2]), tshrink(acc0[3]));
                *(float4*)&h1[(u0+1)*36 + r0] =
                    make_float4(tshrink(acc1[0]), tshrink(acc1[1]), tshrink(acc1[2]), tshrink(acc1[3]));
            }
            __syncthreads();

            // layer 2
            {
                float2 bb = *(const float2*)&b2[u0];
                float acc0[4] = {bb.x, bb.x, bb.x, bb.x};
                float acc1[4] = {bb.y, bb.y, bb.y, bb.y};
                #pragma unroll 4
                for (int d = 0; d < UU; d++) {
                    float2 w = *(const float2*)&W2[d*UU + u0];
                    float4 xa = *(const float4*)&h1[d*36 + r0];
                    acc0[0] += xa.x*w.x; acc0[1] += xa.y*w.x; acc0[2] += xa.z*w.x; acc0[3] += xa.w*w.x;
                    acc1[0] += xa.x*w.y; acc1[1] += xa.y*w.y; acc1[2] += xa.z*w.y; acc1[3] += xa.w*w.y;
                }
                *(float4*)&h2[u0*36 + r0] =
                    make_float4(tshrink(acc0[0]), tshrink(acc0[1]), tshrink(acc0[2]), tshrink(acc0[3]));
                *(float4*)&h2[(u0+1)*36 + r0] =
                    make_float4(tshrink(acc1[0]), tshrink(acc1[1]), tshrink(acc1[2]), tshrink(acc1[3]));
            }
            __syncthreads();

            // layer 3
            {
                int r = t2 >> 3, s8 = t2 & 7;
                float acc = 0.0f;
                #pragma unroll
                for (int k = 0; k < 8; k++) {
                    int uu = s8 + 8*k;
                    acc += h2[uu*36 + r] * W3[uu];
                }
                acc += __shfl_xor_sync(0xffffffffu, acc, 1);
                acc += __shfl_xor_sync(0xffffffffu, acc, 2);
                acc += __shfl_xor_sync(0xffffffffu, acc, 4);
                if (s8 == 0) g_chi[grow0 + r] = tshrink(acc + b3[0]);
            }
            __syncthreads();
        }

        // publish g_Linv (rank0) / g_chi chunk (rank1) to the cluster
        __threadfence();
        CLUSTER_SYNC();

        // rank 1 rebuilds Xt from g_Linv (coalesced read, conflict-free write)
        if (rank == 1) {
            const float* Xb = g_Linv + ((size_t)s*BB + b)*NB*NB;
            for (int idx = tid; idx < NB*NB; idx += 512) {
                int i = idx>>6, j = idx & 63;
                Xt[j*65 + i] = Xb[idx];
            }
        }
        __syncthreads();

        if (R == 0) break;
        const int M2 = R*NB;

        // ---- load OWN A21 tiles transposed: P[k][i] = A[k0+64+i][k0+k]
        for (int t = rank; t < R; t += 2)
            for (int idx = tid; idx < NB*NB; idx += 512) {
                int i = t*64 + (idx>>6), k = idx & 63;
                P[k*PSTRIDE + i] = Mb[(size_t)(k0 + NB + i)*NN + k0 + k];
            }
        __syncthreads();

        // ---- trsm on own tiles: L21 = A21 * invL11^T  (2x4 microtile)
        {
            const int ty = tid >> 4, tx = tid & 15;
            for (int t = rank; t < R; t += 2) {
                const int r0 = t*64 + 2*ty;
                float acc[2][4] = {};
                #pragma unroll 4
                for (int k = 0; k < NB; k++) {
                    float a0 = P[k*PSTRIDE + r0];
                    float a1 = P[k*PSTRIDE + r0 + 1];
                    const float* xr = Xt + k*65 + 4*tx;
                    float x0 = xr[0], x1 = xr[1], x2 = xr[2], x3 = xr[3];
                    acc[0][0] += a0*x0; acc[0][1] += a0*x1; acc[0][2] += a0*x2; acc[0][3] += a0*x3;
                    acc[1][0] += a1*x0; acc[1][1] += a1*x1; acc[1][2] += a1*x2; acc[1][3] += a1*x3;
                }
                __syncthreads();
                #pragma unroll
                for (int u = 0; u < 2; u++) {
                    *(float4*)(Mb + (size_t)(k0 + NB + r0 + u)*NN + k0 + 4*tx) =
                        make_float4(acc[u][0], acc[u][1], acc[u][2], acc[u][3]);
                    P[(4*tx+0)*PSTRIDE + r0 + u] = acc[u][0];
                    P[(4*tx+1)*PSTRIDE + r0 + u] = acc[u][1];
                    P[(4*tx+2)*PSTRIDE + r0 + u] = acc[u][2];
                    P[(4*tx+3)*PSTRIDE + r0 + u] = acc[u][3];
                }
                __syncthreads();
            }
        }

        __threadfence();
        CLUSTER_SYNC();

        // ---- fetch peer CTA's L21 tiles from global into P
        for (int t = rank ^ 1; t < R; t += 2)
            for (int idx = tid; idx < NB*NB; idx += 512) {
                int i = t*64 + (idx>>6), k = idx & 63;
                P[k*PSTRIDE + i] = Mb[(size_t)(k0 + NB + i)*NN + k0 + k];
            }
        __syncthreads();

        // ---- NEW: dump panel (= L21^T) coalesced into g_PT, split by rank.
        // g_PT[s][k][i] = P[k][i] = L[k0+64+i][k0+k]
        {
            float* pt = g_PT + ((size_t)s*BB + b)*NB*PTROW;
            for (int k = rank*32; k < rank*32 + 32; k++)
                for (int i = tid; i < M2; i += 512)
                    pt[k*PTROW + i] = P[k*PSTRIDE + i];
        }

        // ---- syrk: C -= L21 * L21^T; 16 tile-groups across the cluster
        {
            const int grp = (rank << 3) | (tid >> 6);   // 0..15
            const int lane = tid & 63;
            const int sy = lane >> 3, sx = lane & 7;
            const int T = R*(R+1)/2;
            for (int tt = grp; tt < T; tt += 16) {
                int ti = 0;
                while ((ti+1)*(ti+2)/2 <= tt) ti++;
                int tj = tt - ti*(ti+1)/2;

                float acc[8][8] = {};
                const int oi = ti*64 + 8*sy;
                const int oj = tj*64 + 8*sx;
                #pragma unroll 2
                for (int k = 0; k < NB; k++) {
                    const float* prow = P + k*PSTRIDE;
                    float av[8], bv[8];
                    #pragma unroll
                    for (int u = 0; u < 8; u++) av[u] = prow[oi + u];
                    #pragma unroll
                    for (int v = 0; v < 8; v++) bv[v] = prow[oj + v];
                    #pragma unroll
                    for (int u = 0; u < 8; u++)
                        #pragma unroll
                        for (int v = 0; v < 8; v++)
                            acc[u][v] += av[u] * bv[v];
                }
                #pragma unroll
                for (int u = 0; u < 8; u++) {
                    float* crow = Mb + (size_t)(k0 + NB + oi + u)*NN + k0 + NB + oj;
                    float4 c0 = *(float4*)(crow);
                    float4 c1 = *(float4*)(crow + 4);
                    c0.x -= acc[u][0]; c0.y -= acc[u][1]; c0.z -= acc[u][2]; c0.w -= acc[u][3];
                    c1.x -= acc[u][4]; c1.y -= acc[u][5]; c1.z -= acc[u][6]; c1.w -= acc[u][7];
                    *(float4*)(crow)     = c0;
                    *(float4*)(crow + 4) = c1;
                }
            }
        }

        __threadfence();
        CLUSTER_SYNC();   // trailing matrix + g_PT visible to both CTAs
    }

    // ======================= SOLVE (1 RHS per CTA) =======================
    float* y  = sh;           // [512]
    float* u  = sh + 512;     // [64]
    float* rd = sh + 576;     // [32]

    const int r = tid >> 3, q = tid & 7;

    y[tid] = rank ? 1.0f : -g_chi[b*NN + tid];
    __syncthreads();

    // ---- forward: L y = rhs  (coalesced direct reads of lower blocks)
    for (int s = 0; s < NSTEPS; s++) {
        float a = 0.0f;
        for (int t = 0; t < s; t++) {
            const float* blk = Mb + (size_t)(s*NB + r)*NN + t*NB;
            #pragma unroll
            for (int k = q; k < NB; k += 8)
                a += blk[k] * y[t*NB + k];
        }
        a += __shfl_xor_sync(0xffffffffu, a, 1);
        a += __shfl_xor_sync(0xffffffffu, a, 2);
        a += __shfl_xor_sync(0xffffffffu, a, 4);
        if (q == 0) u[r] = y[s*NB + r] - a;
        __syncthreads();

        const float* Xb = g_Linv + ((size_t)s*BB + b)*NB*NB;
        float z = 0.0f;
        #pragma unroll
        for (int k = q; k < NB; k += 8)
            z += Xb[r*NB + k] * u[k];
        z += __shfl_xor_sync(0xffffffffu, z, 1);
        z += __shfl_xor_sync(0xffffffffu, z, 2);
        z += __shfl_xor_sync(0xffffffffu, z, 4);
        if (q == 0) y[s*NB + r] = z;
        __syncthreads();
    }

    // ---- backward: L^T x = y  (stagingless: coalesced reads of g_PT)
    // L^T(s,t)[r][kk] = g_PT[s][r][(t-s-1)*64 + kk]
    for (int s = NSTEPS - 1; s >= 0; s--) {
        const float* pt = g_PT + ((size_t)s*BB + b)*NB*PTROW + r*PTROW;
        float a = 0.0f;
        for (int t = s + 1; t < NSTEPS; t++) {
            const float* blk = pt + (t - s - 1)*64;
            #pragma unroll
            for (int k = q; k < NB; k += 8)
                a += blk[k] * y[t*NB + k];
        }
        a += __shfl_xor_sync(0xffffffffu, a, 1);
        a += __shfl_xor_sync(0xffffffffu, a, 2);
        a += __shfl_xor_sync(0xffffffffu, a, 4);
        if (q == 0) u[r] = y[s*NB + r] - a;
        __syncthreads();

        const float* XbT = g_LinvT + ((size_t)s*BB + b)*NB*NB;
        float z = 0.0f;
        #pragma unroll
        for (int k = q; k < NB; k += 8)
            z += XbT[r*NB + k] * u[k];   // (invL^T)[r][k]
        z += __shfl_xor_sync(0xffffffffu, z, 1);
        z += __shfl_xor_sync(0xffffffffu, z, 2);
        z += __shfl_xor_sync(0xffffffffu, z, 4);
        if (q == 0) y[s*NB + r] = z;
        __syncthreads();
    }

    // ---- handoff x2 and combine on rank 0
    if (rank == 1) g_xv[b*NN + tid] = y[tid];
    __threadfence();
    CLUSTER_SYNC();

    if (rank == 0) {
        float x2 = g_xv[b*NN + tid];
        float s1 = y[tid], s2 = x2;
        #pragma unroll
        for (int o = 16; o > 0; o >>= 1) {
            s1 += __shfl_xor_sync(0xffffffffu, s1, o);
            s2 += __shfl_xor_sync(0xffffffffu, s2, o);
        }
        if ((tid & 31) == 0) { rd[tid >> 5] = s1; rd[16 + (tid >> 5)] = s2; }
        __syncthreads();
        if (tid == 0) {
            float S1 = 0.0f, S2 = 0.0f;
            for (int w = 0; w < 16; w++) { S1 += rd[w]; S2 += rd[16 + w]; }
            rd[0] = (S1 - tq[b]) / S2;
        }
        __syncthreads();
        float mu = rd[0];
        outC[b*NN + tid] = y[tid] - mu * x2;
    }
}

// ---------------------------------------------------------------------------
extern "C" void kernel_launch(void* const* d_in, const int* in_sizes, int n_in,
                              void* d_out, int out_size)
{
    const float* pos   = (const float*)d_in[0];
    const float* nf    = (const float*)d_in[1];
    const int*   ntype = (const int*)  d_in[2];
    const float* tq    = (const float*)d_in[3];
    const float* hard  = (const float*)d_in[4];
    const float* sig   = (const float*)d_in[5];
    const float* W1    = (const float*)d_in[6];
    const float* b1    = (const float*)d_in[7];
    const float* W2    = (const float*)d_in[8];
    const float* b2    = (const float*)d_in[9];
    const float* W3    = (const float*)d_in[10];
    const float* b3    = (const float*)d_in[11];

    float* outC = (float*)d_out;          // charges (B,N)
    float* outA = (float*)d_out + BB*NN;  // A (B,N,N)

    cudaFuncSetAttribute(factor_solve_kernel,
                         cudaFuncAttributeMaxDynamicSharedMemorySize, SMEM_BYTES);

    buildA_kernel<<<dim3(NN/32, NN/32, BB), 256>>>(pos, ntype, hard, sig, outA);
    factor_solve_kernel<<<2*BB, 512, SMEM_BYTES>>>(tq, outC,
                                                   nf, W1, b1, W2, b2, W3, b3);
}

// round 17
// speedup vs baseline: 1.0386x; 1.0386x over previous
#include <cuda_runtime.h>
#include <math.h>

#define BB 64
#define NN 512
#define DD 128
#define UU 64
#define NB 64
#define NSTEPS (NN/NB)

#define PSTRIDE 449              // odd -> conflict-free transposed panel stores
#define OFF_S   28736            // 64*449 (P panel)
#define OFF_X   (OFF_S + 64*65)
#define OFF_XT  (OFF_X + 64*65)
#define OFF_TT  (OFF_XT + 64*65)
#define OFF_DI  (OFF_TT + 32*33)
#define SMEM_FLOATS (OFF_DI + 64)
#define SMEM_BYTES (SMEM_FLOATS*4)

// Scratch (allocation-free rule: __device__ globals)
__device__ float g_M[BB*NN*NN];              // Cholesky workspace (copy of A)
__device__ float g_chi[BB*NN];
__device__ float g_Linv[NSTEPS*BB*NB*NB];    // inv of each diagonal block L11
__device__ float g_LinvT[NSTEPS*BB*NB*NB];   // transposed inverses (backward diag)
__device__ float g_xv[BB*NN];                // x2 handoff (rank1 -> rank0)

__device__ __forceinline__ float tshrink(float x) { return x - tanhf(x); }

#define CLUSTER_SYNC() do { \
    asm volatile("barrier.cluster.arrive.aligned;" ::: "memory"); \
    asm volatile("barrier.cluster.wait.aligned;" ::: "memory"); \
} while(0)

// ---------------------------------------------------------------------------
// Build A (B,N,N): 32x32 tile per block, write to output AND scratch
// ---------------------------------------------------------------------------
__global__ __launch_bounds__(256) void buildA_kernel(
    const float* __restrict__ pos,
    const int*   __restrict__ ntype,
    const float* __restrict__ hardness,
    const float* __restrict__ sigma,
    float* __restrict__ outA)
{
    __shared__ float pix[32], piy[32], piz[32];
    __shared__ float pjx[32], pjy[32], pjz[32];
    __shared__ float si[32], sj[32], hi[32];

    const int b  = blockIdx.z;
    const int it = blockIdx.y, jt = blockIdx.x;
    const int tid = threadIdx.x;
    const float kC = 14.399645351950548f;

    if (tid < 32) {
        int gi = it*32 + tid;
        const float* p = pos + ((size_t)b*NN + gi)*3;
        pix[tid]=p[0]; piy[tid]=p[1]; piz[tid]=p[2];
        int t = ntype[b*NN + gi];
        si[tid] = sigma[t]; hi[tid] = hardness[t];
    } else if (tid < 64) {
        int l = tid - 32;
        int gj = jt*32 + l;
        const float* p = pos + ((size_t)b*NN + gj)*3;
        pjx[l]=p[0]; pjy[l]=p[1]; pjz[l]=p[2];
        sj[l] = sigma[ntype[b*NN + gj]];
    }
    __syncthreads();

    float* Ab = outA + (size_t)b*NN*NN;
    float* Mb = g_M  + (size_t)b*NN*NN;

    for (int e = tid; e < 32*32; e += 256) {
        int li = e >> 5, lj = e & 31;
        int i = it*32 + li, j = jt*32 + lj;
        float dx = pix[li]-pjx[lj], dy = piy[li]-pjy[lj], dz = piz[li]-pjz[lj];
        float dist = sqrtf(dx*dx + dy*dy + dz*dz) + 1e-8f;
        float g2 = si[li]*si[li] + sj[lj]*sj[lj];
        float arg = dist * rsqrtf(2.0f * g2);
        float a = kC * erff(arg) / dist;
        if (i == j) {
            a += hi[li] + kC / (1.7724538509055159f * 1.4142135623730951f * si[li]);
        }
        size_t off = (size_t)i*NN + j;
        Ab[off] = a;
        Mb[off] = a;
    }
}

// ---------------------------------------------------------------------------
// Fused per-batch Cholesky + triangular solves + Schur combine.
// 2-CTA cluster per batch. Rank 0: potrf; rank 1: chi chunk (hidden).
// R15 structure; panel loads vectorized to LDG.128.
// ---------------------------------------------------------------------------
extern __shared__ float sh[];

__global__ __launch_bounds__(512, 1) __cluster_dims__(2, 1, 1)
void factor_solve_kernel(const float* __restrict__ tq, float* __restrict__ outC,
                         const float* __restrict__ nf,
                         const float* __restrict__ W1, const float* __restrict__ b1,
                         const float* __restrict__ W2, const float* __restrict__ b2,
                         const float* __restrict__ W3, const float* __restrict__ b3)
{
    const int b    = blockIdx.x >> 1;
    const int rank = blockIdx.x & 1;
    const int tid  = threadIdx.x;  // 512
    float* Mb = g_M + (size_t)b*NN*NN;

    float* P  = sh;
    float* Sd = sh + OFF_S;    // [64][65] diag block
    float* Xi = sh + OFF_X;    // [64][65] invL
    float* Xt = sh + OFF_XT;   // [64][65] invL transposed
    float* Tt = sh + OFF_TT;   // [32][33]
    float* di = sh + OFF_DI;   // [64]

    // ======================= FACTORIZATION =======================
    for (int s = 0; s < NSTEPS; s++) {
        const int k0 = s*NB;
        const int R  = NSTEPS - 1 - s;

        if (rank == 0) {
            // ---- load diagonal block
            for (int idx = tid; idx < NB*NB; idx += 512)
                Sd[(idx>>6)*65 + (idx&63)] = Mb[(size_t)(k0 + (idx>>6))*NN + k0 + (idx&63)];
            __syncthreads();

            // ---- LDL-style elimination, 1 barrier/iter, all 512 threads
            for (int j = 0; j < NB; j++) {
                float invd = 1.0f / Sd[j*65 + j];
                int cnt = (63 - j) * 64;
                for (int idx = tid; idx < cnt; idx += 512) {
                    int i = j + 1 + (idx>>6), c = idx & 63;
                    if (c > j && i >= c)
                        Sd[i*65 + c] -= Sd[i*65 + j] * (Sd[c*65 + j] * invd);
                }
                __syncthreads();
            }
            if (tid < NB) di[tid] = rsqrtf(Sd[tid*65 + tid]);
            __syncthreads();
            for (int idx = tid; idx < NB*NB; idx += 512) {
                int i = idx>>6, c = idx & 63;
                if (i >= c) Sd[i*65 + c] *= di[c];
            }
            __syncthreads();

            // ---- invert L11 (block 2x2): two warp-local 32x32 inversions
            if (tid < 64) {
                int h = tid >> 5, j = tid & 31, base = h*32;
                for (int i = 0; i < 32; i++) {
                    float acc = (i == j) ? 1.0f : 0.0f;
                    for (int p = 0; p < i; p++)
                        acc -= Sd[(base+i)*65 + base+p] * Xi[(base+p)*65 + base+j];
                    Xi[(base+i)*65 + base+j] = acc * di[base+i];
                    __syncwarp();
                }
            }
            __syncthreads();
            for (int idx = tid; idx < 32*32; idx += 512) {
                int i = idx>>5, j = idx & 31;
                float acc = 0.0f;
                #pragma unroll 8
                for (int p = 0; p < 32; p++) acc += Sd[(32+i)*65 + p] * Xi[p*65 + j];
                Tt[i*33 + j] = acc;
                Xi[i*65 + 32 + j] = 0.0f;
            }
            __syncthreads();
            for (int idx = tid; idx < 32*32; idx += 512) {
                int i = idx>>5, j = idx & 31;
                float acc = 0.0f;
                #pragma unroll 8
                for (int p = 0; p < 32; p++) acc += Xi[(32+i)*65 + 32+p] * Tt[p*33 + j];
                Xi[(32+i)*65 + j] = -acc;
            }
            __syncthreads();

            // write g_Linv/g_LinvT (coalesced) + smem Xt[k][j] = invL[j][k]
            {
                float* Xb  = g_Linv  + ((size_t)s*BB + b)*NB*NB;
                float* XbT = g_LinvT + ((size_t)s*BB + b)*NB*NB;
                for (int idx = tid; idx < NB*NB; idx += 512) {
                    int i = idx>>6, j = idx & 63;
                    float v = Xi[i*65 + j];
                    Xb[idx] = v;
                    Xt[j*65 + i] = v;
                    XbT[idx] = Xi[j*65 + i];
                }
            }
            __syncthreads();
        } else {
            // ---- rank 1: chi MLP for rows s*64 .. s*64+63 of batch b.
            const int h  = tid >> 8;          // 0 or 1
            const int t2 = tid & 255;
            float* xs = P + h*9216;           // [128][36]
            float* h1 = xs + 4608;            // [64][36]
            float* h2 = xs + 6912;            // [64][36]
            const int grow0 = b*NN + s*64 + h*32;
            const int u0 = 2*(t2 >> 3);
            const int r0 = 4*(t2 & 7);

            #pragma unroll
            for (int t = 0; t < 4; t++) {
                int f = t2 + 256*t;
                int r = f >> 5, c4 = f & 31;
                float4 v = *(const float4*)(nf + (size_t)(grow0 + r)*DD + c4*4);
                xs[(c4*4+0)*36 + r] = v.x;
                xs[(c4*4+1)*36 + r] = v.y;
                xs[(c4*4+2)*36 + r] = v.z;
                xs[(c4*4+3)*36 + r] = v.w;
            }
            __syncthreads();

            // layer 1
            {
                float2 bb = *(const float2*)&b1[u0];
                float acc0[4] = {bb.x, bb.x, bb.x, bb.x};
                float acc1[4] = {bb.y, bb.y, bb.y, bb.y};
                #pragma unroll 4
                for (int d = 0; d < DD; d++) {
                    float2 w = *(const float2*)&W1[d*UU + u0];
                    float4 xa = *(const float4*)&xs[d*36 + r0];
                    acc0[0] += xa.x*w.x; acc0[1] += xa.y*w.x; acc0[2] += xa.z*w.x; acc0[3] += xa.w*w.x;
                    acc1[0] += xa.x*w.y; acc1[1] += xa.y*w.y; acc1[2] += xa.z*w.y; acc1[3] += xa.w*w.y;
                }
                *(float4*)&h1[u0*36 + r0] =
                    make_float4(tshrink(acc0[0]), tshrink(acc0[1]), tshrink(acc0[2]), tshrink(acc0[3]));
                *(float4*)&h1[(u0+1)*36 + r0] =
                    make_float4(tshrink(acc1[0]), tshrink(acc1[1]), tshrink(acc1[2]), tshrink(acc1[3]));
            }
            __syncthreads();

            // layer 2
            {
                float2 bb = *(const float2*)&b2[u0];
                float acc0[4] = {bb.x, bb.x, bb.x, bb.x};
                float acc1[4] = {bb.y, bb.y, bb.y, bb.y};
                #pragma unroll 4
                for (int d = 0; d < UU; d++) {
                    float2 w = *(const float2*)&W2[d*UU + u0];
                    float4 xa = *(const float4*)&h1[d*36 + r0];
                    acc0[0] += xa.x*w.x; acc0[1] += xa.y*w.x; acc0[2] += xa.z*w.x; acc0[3] += xa.w*w.x;
                    acc1[0] += xa.x*w.y; acc1[1] += xa.y*w.y; acc1[2] += xa.z*w.y; acc1[3] += xa.w*w.y;
                }
                *(float4*)&h2[u0*36 + r0] =
                    make_float4(tshrink(acc0[0]), tshrink(acc0[1]), tshrink(acc0[2]), tshrink(acc0[3]));
                *(float4*)&h2[(u0+1)*36 + r0] =
                    make_float4(tshrink(acc1[0]), tshrink(acc1[1]), tshrink(acc1[2]), tshrink(acc1[3]));
            }
            __syncthreads();

            // layer 3
            {
                int r = t2 >> 3, s8 = t2 & 7;
                float acc = 0.0f;
                #pragma unroll
                for (int k = 0; k < 8; k++) {
                    int uu = s8 + 8*k;
                    acc += h2[uu*36 + r] * W3[uu];
                }
                acc += __shfl_xor_sync(0xffffffffu, acc, 1);
                acc += __shfl_xor_sync(0xffffffffu, acc, 2);
                acc += __shfl_xor_sync(0xffffffffu, acc, 4);
                if (s8 == 0) g_chi[grow0 + r] = tshrink(acc + b3[0]);
            }
            __syncthreads();
        }

        // publish g_Linv (rank0) / g_chi chunk (rank1) to the cluster
        __threadfence();
        CLUSTER_SYNC();

        // rank 1 rebuilds Xt from g_Linv (coalesced read, conflict-free write)
        if (rank == 1) {
            const float* Xb = g_Linv + ((size_t)s*BB + b)*NB*NB;
            for (int idx = tid; idx < NB*NB; idx += 512) {
                int i = idx>>6, j = idx & 63;
                Xt[j*65 + i] = Xb[idx];
            }
        }
        __syncthreads();

        if (R == 0) break;

        // ---- load OWN A21 tiles transposed (LDG.128): P[k][i] = A[k0+64+i][k0+k]
        for (int t = rank; t < R; t += 2)
            for (int idx = tid; idx < NB*NB/4; idx += 512) {
                int i  = t*64 + (idx >> 4);
                int k4 = (idx & 15) * 4;
                float4 v = *(const float4*)(Mb + (size_t)(k0 + NB + i)*NN + k0 + k4);
                P[(k4+0)*PSTRIDE + i] = v.x;
                P[(k4+1)*PSTRIDE + i] = v.y;
                P[(k4+2)*PSTRIDE + i] = v.z;
                P[(k4+3)*PSTRIDE + i] = v.w;
            }
        __syncthreads();

        // ---- trsm on own tiles: L21 = A21 * invL11^T  (2x4 microtile)
        {
            const int ty = tid >> 4, tx = tid & 15;
            for (int t = rank; t < R; t += 2) {
                const int r0 = t*64 + 2*ty;
                float acc[2][4] = {};
                #pragma unroll 4
                for (int k = 0; k < NB; k++) {
                    float a0 = P[k*PSTRIDE + r0];
                    float a1 = P[k*PSTRIDE + r0 + 1];
                    const float* xr = Xt + k*65 + 4*tx;
                    float x0 = xr[0], x1 = xr[1], x2 = xr[2], x3 = xr[3];
                    acc[0][0] += a0*x0; acc[0][1] += a0*x1; acc[0][2] += a0*x2; acc[0][3] += a0*x3;
                    acc[1][0] += a1*x0; acc[1][1] += a1*x1; acc[1][2] += a1*x2; acc[1][3] += a1*x3;
                }
                __syncthreads();
                #pragma unroll
                for (int u = 0; u < 2; u++) {
                    *(float4*)(Mb + (size_t)(k0 + NB + r0 + u)*NN + k0 + 4*tx) =
                        make_float4(acc[u][0], acc[u][1], acc[u][2], acc[u][3]);
                    P[(4*tx+0)*PSTRIDE + r0 + u] = acc[u][0];
                    P[(4*tx+1)*PSTRIDE + r0 + u] = acc[u][1];
                    P[(4*tx+2)*PSTRIDE + r0 + u] = acc[u][2];
                    P[(4*tx+3)*PSTRIDE + r0 + u] = acc[u][3];
                }
                __syncthreads();
            }
        }

        __threadfence();
        CLUSTER_SYNC();

        // ---- fetch peer CTA's L21 tiles from global into P (LDG.128)
        for (int t = rank ^ 1; t < R; t += 2)
            for (int idx = tid; idx < NB*NB/4; idx += 512) {
                int i  = t*64 + (idx >> 4);
                int k4 = (idx & 15) * 4;
                float4 v = *(const float4*)(Mb + (size_t)(k0 + NB + i)*NN + k0 + k4);
                P[(k4+0)*PSTRIDE + i] = v.x;
                P[(k4+1)*PSTRIDE + i] = v.y;
                P[(k4+2)*PSTRIDE + i] = v.z;
                P[(k4+3)*PSTRIDE + i] = v.w;
            }
        __syncthreads();

        // ---- syrk: C -= L21 * L21^T; 16 tile-groups across the cluster
        {
            const int grp = (rank << 3) | (tid >> 6);   // 0..15
            const int lane = tid & 63;
            const int sy = lane >> 3, sx = lane & 7;
            const int T = R*(R+1)/2;
            for (int tt = grp; tt < T; tt += 16) {
                int ti = 0;
                while ((ti+1)*(ti+2)/2 <= tt) ti++;
                int tj = tt - ti*(ti+1)/2;

                float acc[8][8] = {};
                const int oi = ti*64 + 8*sy;
                const int oj = tj*64 + 8*sx;
                #pragma unroll 2
                for (int k = 0; k < NB; k++) {
                    const float* prow = P + k*PSTRIDE;
                    float av[8], bv[8];
                    #pragma unroll
                    for (int u = 0; u < 8; u++) av[u] = prow[oi + u];
                    #pragma unroll
                    for (int v = 0; v < 8; v++) bv[v] = prow[oj + v];
                    #pragma unroll
                    for (int u = 0; u < 8; u++)
                        #pragma unroll
                        for (int v = 0; v < 8; v++)
                            acc[u][v] += av[u] * bv[v];
                }
                #pragma unroll
                for (int u = 0; u < 8; u++) {
                    float* crow = Mb + (size_t)(k0 + NB + oi + u)*NN + k0 + NB + oj;
                    float4 c0 = *(float4*)(crow);
                    float4 c1 = *(float4*)(crow + 4);
                    c0.x -= acc[u][0]; c0.y -= acc[u][1]; c0.z -= acc[u][2]; c0.w -= acc[u][3];
                    c1.x -= acc[u][4]; c1.y -= acc[u][5]; c1.z -= acc[u][6]; c1.w -= acc[u][7];
                    *(float4*)(crow)     = c0;
                    *(float4*)(crow + 4) = c1;
                }
            }
        }

        __threadfence();
        CLUSTER_SYNC();   // trailing matrix visible to both CTAs before next step
    }

    // ======================= SOLVE (1 RHS per CTA) =======================
    float* y  = sh;           // [512]
    float* u  = sh + 512;     // [64]
    float* rd = sh + 576;     // [32]
    float* Bs = sh + OFF_X;   // [64][65] staging (backward off-diag blocks)

    const int r = tid >> 3, q = tid & 7;

    y[tid] = rank ? 1.0f : -g_chi[b*NN + tid];
    __syncthreads();

    // ---- forward: L y = rhs  (coalesced direct reads of lower blocks)
    for (int s = 0; s < NSTEPS; s++) {
        float a = 0.0f;
        for (int t = 0; t < s; t++) {
            const float* blk = Mb + (size_t)(s*NB + r)*NN + t*NB;
            #pragma unroll
            for (int k = q; k < NB; k += 8)
                a += blk[k] * y[t*NB + k];
        }
        a += __shfl_xor_sync(0xffffffffu, a, 1);
        a += __shfl_xor_sync(0xffffffffu, a, 2);
        a += __shfl_xor_sync(0xffffffffu, a, 4);
        if (q == 0) u[r] = y[s*NB + r] - a;
        __syncthreads();

        const float* Xb = g_Linv + ((size_t)s*BB + b)*NB*NB;
        float z = 0.0f;
        #pragma unroll
        for (int k = q; k < NB; k += 8)
            z += Xb[r*NB + k] * u[k];
        z += __shfl_xor_sync(0xffffffffu, z, 1);
        z += __shfl_xor_sync(0xffffffffu, z, 2);
        z += __shfl_xor_sync(0xffffffffu, z, 4);
        if (q == 0) y[s*NB + r] = z;
        __syncthreads();
    }

    // ---- backward: L^T x = y  (stage off-diag blocks; diag via g_LinvT)
    for (int s = NSTEPS - 1; s >= 0; s--) {
        float a = 0.0f;
        for (int t = s + 1; t < NSTEPS; t++) {
            for (int idx = tid; idx < NB*NB; idx += 512) {
                int k = idx>>6, c = idx & 63;
                Bs[k*65 + c] = Mb[(size_t)(t*NB + k)*NN + s*NB + c];
            }
            __syncthreads();
            #pragma unroll
            for (int k = q; k < NB; k += 8)
                a += Bs[k*65 + r] * y[t*NB + k];
            __syncthreads();
        }
        a += __shfl_xor_sync(0xffffffffu, a, 1);
        a += __shfl_xor_sync(0xffffffffu, a, 2);
        a += __shfl_xor_sync(0xffffffffu, a, 4);
        if (q == 0) u[r] = y[s*NB + r] - a;
        __syncthreads();

        const float* XbT = g_LinvT + ((size_t)s*BB + b)*NB*NB;
        float z = 0.0f;
        #pragma unroll
        for (int k = q; k < NB; k += 8)
            z += XbT[r*NB + k] * u[k];   // (invL^T)[r][k]
        z += __shfl_xor_sync(0xffffffffu, z, 1);
        z += __shfl_xor_sync(0xffffffffu, z, 2);
        z += __shfl_xor_sync(0xffffffffu, z, 4);
        if (q == 0) y[s*NB + r] = z;
        __syncthreads();
    }

    // ---- handoff x2 and combine on rank 0
    if (rank == 1) g_xv[b*NN + tid] = y[tid];
    __threadfence();
    CLUSTER_SYNC();

    if (rank == 0) {
        float x2 = g_xv[b*NN + tid];
        float s1 = y[tid], s2 = x2;
        #pragma unroll
        for (int o = 16; o > 0; o >>= 1) {
            s1 += __shfl_xor_sync(0xffffffffu, s1, o);
            s2 += __shfl_xor_sync(0xffffffffu, s2, o);
        }
        if ((tid & 31) == 0) { rd[tid >> 5] = s1; rd[16 + (tid >> 5)] = s2; }
        __syncthreads();
        if (tid == 0) {
            float S1 = 0.0f, S2 = 0.0f;
            for (int w = 0; w < 16; w++) { S1 += rd[w]; S2 += rd[16 + w]; }
            rd[0] = (S1 - tq[b]) / S2;
        }
        __syncthreads();
        float mu = rd[0];
        outC[b*NN + tid] = y[tid] - mu * x2;
    }
}

// ---------------------------------------------------------------------------
extern "C" void kernel_launch(void* const* d_in, const int* in_sizes, int n_in,
                              void* d_out, int out_size)
{
    const float* pos   = (const float*)d_in[0];
    const float* nf    = (const float*)d_in[1];
    const int*   ntype = (const int*)  d_in[2];
    const float* tq    = (const float*)d_in[3];
    const float* hard  = (const float*)d_in[4];
    const float* sig   = (const float*)d_in[5];
    const float* W1    = (const float*)d_in[6];
    const float* b1    = (const float*)d_in[7];
    const float* W2    = (const float*)d_in[8];
    const float* b2    = (const float*)d_in[9];
    const float* W3    = (const float*)d_in[10];
    const float* b3    = (const float*)d_in[11];

    float* outC = (float*)d_out;          // charges (B,N)
    float* outA = (float*)d_out + BB*NN;  // A (B,N,N)

    cudaFuncSetAttribute(factor_solve_kernel,
                         cudaFuncAttributeMaxDynamicSharedMemorySize, SMEM_BYTES);

    buildA_kernel<<<dim3(NN/32, NN/32, BB), 256>>>(pos, ntype, hard, sig, outA);
    factor_solve_kernel<<<2*BB, 512, SMEM_BYTES>>>(tq, outC,
                                                   nf, W1, b1, W2, b2, W3, b3);
}